// round 1
// baseline (speedup 1.0000x reference)
#include <cuda_runtime.h>
#include <math.h>

#define NT 16384   // tokens = B*S
#define HH 2048    // hidden
#define NE 64      // experts
#define NB 4       // batch
#define NS 4096    // seq
#define TM 64      // tokens per block
#define KC 32      // k chunk

// scratch for aux-loss reduction (allocation-free rule: __device__ globals)
__device__ float g_ssum[NB * NE];
__device__ int   g_cnt[NB * NE];

__global__ void k_zero() {
    int i = threadIdx.x;
    g_ssum[i] = 0.0f;
    g_cnt[i]  = 0;
}

__global__ __launch_bounds__(256) void k_gate(const float* __restrict__ X,
                                              const float* __restrict__ W,
                                              float* __restrict__ out,
                                              int wbase) {
    // smem: staging buffers, reused as logits [64][65] in epilogue
    __shared__ float smem[2 * 64 * 33];
    float (*xs)[33] = (float (*)[33])smem;
    float (*ws)[33] = (float (*)[33])(smem + 64 * 33);
    __shared__ int cnt[NE];

    const int tid = threadIdx.x;
    const int tx  = tid & 15;   // expert dir
    const int ty  = tid >> 4;   // token dir
    const int tokBase = blockIdx.x * TM;

    float acc[4][4];
#pragma unroll
    for (int i = 0; i < 4; i++)
#pragma unroll
        for (int j = 0; j < 4; j++) acc[i][j] = 0.0f;

    for (int k0 = 0; k0 < HH; k0 += KC) {
        // load x tile [64 tok][32 k] and w tile [64 exp][32 k], float4 per thread x2
#pragma unroll
        for (int p = 0; p < 2; p++) {
            int f4  = tid + p * 256;     // 0..511
            int row = f4 >> 3;
            int c4  = f4 & 7;
            float4 vx = *(const float4*)(X + (size_t)(tokBase + row) * HH + k0 + c4 * 4);
            xs[row][c4 * 4 + 0] = vx.x;
            xs[row][c4 * 4 + 1] = vx.y;
            xs[row][c4 * 4 + 2] = vx.z;
            xs[row][c4 * 4 + 3] = vx.w;
            float4 vw = *(const float4*)(W + (size_t)row * HH + k0 + c4 * 4);
            ws[row][c4 * 4 + 0] = vw.x;
            ws[row][c4 * 4 + 1] = vw.y;
            ws[row][c4 * 4 + 2] = vw.z;
            ws[row][c4 * 4 + 3] = vw.w;
        }
        __syncthreads();
#pragma unroll
        for (int k = 0; k < KC; k++) {
            float a[4], b[4];
#pragma unroll
            for (int i = 0; i < 4; i++) a[i] = xs[ty + 16 * i][k];
#pragma unroll
            for (int j = 0; j < 4; j++) b[j] = ws[tx + 16 * j][k];
#pragma unroll
            for (int i = 0; i < 4; i++)
#pragma unroll
                for (int j = 0; j < 4; j++) acc[i][j] += a[i] * b[j];
        }
        __syncthreads();
    }

    // --- epilogue: logits -> smem [64][65] (aliases staging buffers) ---
    float (*L)[65] = (float (*)[65])smem;
#pragma unroll
    for (int i = 0; i < 4; i++)
#pragma unroll
        for (int j = 0; j < 4; j++)
            L[ty + 16 * i][tx + 16 * j] = acc[i][j];
    if (tid < NE) cnt[tid] = 0;
    __syncthreads();

    if (tid < TM) {
        const int t = tid;
        float m = -1e30f;
#pragma unroll
        for (int e = 0; e < NE; e++) m = fmaxf(m, L[t][e]);

        float Z = 0.0f;
        float b1 = -1e30f, b2 = -1e30f;
        int   i1 = 0,      i2 = 0;
        for (int e = 0; e < NE; e++) {
            float v  = L[t][e];
            float ex = expf(v - m);
            L[t][e]  = ex;          // store numerator in place
            Z += ex;
            if (v > b1) { b2 = b1; i2 = i1; b1 = v; i1 = e; }
            else if (v > b2) { b2 = v; i2 = e; }
        }
        float invZ = 1.0f / Z;
        float s1 = L[t][i1] * invZ;
        float s2 = L[t][i2] * invZ;
        float den = s1 + s2 + 1e-20f;
        float w1 = s1 / den;
        float w2 = s2 / den;

        int gt = tokBase + t;
        out[gt * 2 + 0] = (float)i1;
        out[gt * 2 + 1] = (float)i2;
        out[wbase + gt * 2 + 0] = w1;
        out[wbase + gt * 2 + 1] = w2;

        atomicAdd(&cnt[i1], 1);
        atomicAdd(&cnt[i2], 1);

        // convert row to probabilities for expert_scores accumulation
        for (int e = 0; e < NE; e++) L[t][e] *= invZ;
    }
    __syncthreads();

    if (tid < NE) {
        const int e = tid;
        float s = 0.0f;
        for (int t = 0; t < TM; t++) s += L[t][e];
        const int b = tokBase >> 12;   // 4096 tokens per batch, TM divides it
        atomicAdd(&g_ssum[b * NE + e], s);
        if (cnt[e]) atomicAdd(&g_cnt[b * NE + e], cnt[e]);
    }
}

__global__ void k_aux(float* __restrict__ out, int aux_idx) {
    __shared__ float red[NB * NE];
    int i = threadIdx.x;  // 0..255 over (b,e)
    // ce = cnt * E/(S*TOPK);  es = ssum / S;  aux = mean_b(sum_e ce*es) * ALPHA
    float v = (float)g_cnt[i] * ((float)NE / (float)(NS * 2)) * (g_ssum[i] / (float)NS);
    red[i] = v;
    __syncthreads();
    for (int s = 128; s > 0; s >>= 1) {
        if (i < s) red[i] += red[i + s];
        __syncthreads();
    }
    if (i == 0) out[aux_idx] = red[0] / (float)NB * 0.1f;
}

extern "C" void kernel_launch(void* const* d_in, const int* in_sizes, int n_in,
                              void* d_out, int out_size) {
    const float* X = (const float*)d_in[0];   // [4,4096,2048] fp32
    const float* W = (const float*)d_in[1];   // [64,2048] fp32
    float* out = (float*)d_out;

    const int wbase = (out_size - 1) / 2;     // 32768: weights region after idx region

    k_zero<<<1, NB * NE>>>();
    k_gate<<<NT / TM, 256>>>(X, W, out, wbase);
    k_aux<<<1, NB * NE>>>(out, out_size - 1);
}